// round 3
// baseline (speedup 1.0000x reference)
#include <cuda_runtime.h>

// GASLayer: per-column EMA normalization scan over T timesteps.
// Exact chunked linear-recurrence scan (3 kernels), no approximation.
// R3: LL=64/CC=512 (occupancy for K1+K3), float2 everywhere, MLP=8 prefetch.

#define TT 32768
#define DD 1024
#define LL 64
#define CC (TT / LL)   // 512 chunks

#define ETA_MU  0.01f
#define ETA_VAR 0.02f
#define A_MU (1.0f - ETA_MU)   // 0.99
#define C_V  (1.0f - ETA_VAR)  // 0.98

// Scratch: chunk-boundary partials (device globals, no allocation). ~14 MB total.
__device__ float g_sum[CC][DD];
__device__ float g_sq [CC][DD];
__device__ float g_b  [CC][DD];   // zero-init mu scan value at chunk end
__device__ float g_p0 [CC][DD];   // sum c^{L-1-t} * eta_v * e_t^2
__device__ float g_p1 [CC][DD];   // sum c^{L-1-t} * eta_v * a^{t+1} * e_t
__device__ float g_ms [CC][DD];   // exact mu at chunk entry
__device__ float g_vs [CC][DD];   // exact var-slot at chunk entry

// Pass 1: chunk-local partials. Each thread owns 2 adjacent columns.
// Grid: (CC, DD/256) = (512, 4) = 2048 blocks of 128 -> ~55 warps/SM.
__global__ __launch_bounds__(128) void gas_k1(const float* __restrict__ x) {
    const int p  = blockIdx.y * 128 + threadIdx.x;  // column-pair index 0..511
    const int c  = blockIdx.x;
    const int hd = DD / 2;
    const float2* xp = (const float2*)(x + (size_t)c * LL * DD) + p;

    float sx = 0.f, sy = 0.f, s2x = 0.f, s2y = 0.f;
    float bx = 0.f, by = 0.f, p0x = 0.f, p0y = 0.f, p1x = 0.f, p1y = 0.f;
    float w = 1.f;

    for (int t = 0; t < LL; t += 8) {
        float2 xb[8];
        #pragma unroll
        for (int u = 0; u < 8; u++) xb[u] = xp[(size_t)(t + u) * hd];
        #pragma unroll
        for (int u = 0; u < 8; u++) {
            float xv = xb[u].x, yv = xb[u].y;
            sx += xv;                 sy += yv;
            s2x = fmaf(xv, xv, s2x);  s2y = fmaf(yv, yv, s2y);
            bx  = fmaf(ETA_MU, xv - bx, bx);
            by  = fmaf(ETA_MU, yv - by, by);
            w  *= A_MU;               // w = a^{t+1}
            float ex = xv - bx, ey = yv - by;
            p0x = fmaf(ETA_VAR * ex, ex, C_V * p0x);
            p0y = fmaf(ETA_VAR * ey, ey, C_V * p0y);
            p1x = fmaf(ETA_VAR * w, ex, C_V * p1x);
            p1y = fmaf(ETA_VAR * w, ey, C_V * p1y);
        }
    }
    ((float2*)g_sum[c])[p] = make_float2(sx, sy);
    ((float2*)g_sq [c])[p] = make_float2(s2x, s2y);
    ((float2*)g_b  [c])[p] = make_float2(bx, by);
    ((float2*)g_p0 [c])[p] = make_float2(p0x, p0y);
    ((float2*)g_p1 [c])[p] = make_float2(p1x, p1y);
}

// Pass 2: mu0/std0 + exact chunk-entry state chain (C steps per column).
__global__ __launch_bounds__(128) void gas_k2() {
    const int d = blockIdx.x * 128 + threadIdx.x;

    float s = 0.f, s2 = 0.f;
    #pragma unroll 8
    for (int c = 0; c < CC; c++) { s += g_sum[c][d]; s2 += g_sq[c][d]; }
    float mu0  = s * (1.0f / TT);
    float varu = (s2 - (float)TT * mu0 * mu0) * (1.0f / (TT - 1));
    float std0 = sqrtf(fmaxf(varu, 0.f));   // torch.std (unbiased), stored in var slot

    // P2 = sum_t c^{L-1-t} * eta_v * a^{2(t+1)}  (universal constant), plus a^L, c^L.
    float p2 = 0.f, w = 1.f, cLp = 1.f;
    for (int t = 0; t < LL; t++) {
        w   *= A_MU;
        p2   = fmaf(ETA_VAR * w, w, C_V * p2);
        cLp *= C_V;
    }
    const float aL = w;
    const float cL = cLp;

    float ms = mu0, vs = std0;
    // Software-pipelined chain: prefetch next chunk's partials.
    float np0 = g_p0[0][d], np1 = g_p1[0][d], nb = g_b[0][d];
    for (int c = 0; c < CC; c++) {
        float cp0 = np0, cp1 = np1, cb = nb;
        if (c + 1 < CC) {
            np0 = g_p0[c + 1][d];
            np1 = g_p1[c + 1][d];
            nb  = g_b [c + 1][d];
        }
        g_ms[c][d] = ms;
        g_vs[c][d] = vs;
        float bv = cp0 - 2.f * ms * cp1 + ms * ms * p2;
        vs = cL * vs + bv;
        ms = aL * ms + cb;
    }
}

// Pass 3: true recurrence from exact entry state; emit all outputs.
// float2-vectorized, 8-row prefetch (MLP=8).
// Grid: (CC, DD/256) = (512, 4) = 2048 blocks of 128 -> ~55 warps/SM.
__global__ __launch_bounds__(128) void gas_k3(const float* __restrict__ x,
                                              float* __restrict__ out) {
    const int p  = blockIdx.y * 128 + threadIdx.x;  // column-pair index 0..511
    const int c  = blockIdx.x;
    const int hd = DD / 2;

    float2 m = ((const float2*)g_ms[c])[p];
    float2 v = ((const float2*)g_vs[c])[p];

    const float2* xp    = (const float2*)(x + (size_t)c * LL * DD) + p;
    float2*       norm2 = (float2*)(out + (size_t)c * LL * DD) + p;
    // info base for this chunk: rows of [mu(D), var(D)] -> DD float2s per row
    float2*       info2 = (float2*)(out + (size_t)TT * DD + (size_t)c * LL * 2 * DD) + p;

    for (int t = 0; t < LL; t += 8) {
        float2 xb[8];
        #pragma unroll
        for (int u = 0; u < 8; u++) xb[u] = xp[(size_t)(t + u) * hd];
        #pragma unroll
        for (int u = 0; u < 8; u++) {
            float2 xv = xb[u];
            m.x = fmaf(ETA_MU, xv.x - m.x, m.x);
            m.y = fmaf(ETA_MU, xv.y - m.y, m.y);
            float rx = xv.x - m.x;
            float ry = xv.y - m.y;
            v.x = fmaf(ETA_VAR * rx, rx, C_V * v.x);
            v.y = fmaf(ETA_VAR * ry, ry, C_V * v.y);
            float2 n;
            n.x = rx * rsqrtf(v.x);
            n.y = ry * rsqrtf(v.y);
            norm2[(size_t)(t + u) * hd]      = n;
            info2[(size_t)(t + u) * DD]      = m;   // mu half of the info row
            info2[(size_t)(t + u) * DD + hd] = v;   // var half of the info row
        }
    }
}

extern "C" void kernel_launch(void* const* d_in, const int* in_sizes, int n_in,
                              void* d_out, int out_size) {
    const float* x = (const float*)d_in[0];
    float* out = (float*)d_out;

    gas_k1<<<dim3(CC, DD / 256), 128>>>(x);
    gas_k2<<<DD / 128, 128>>>();
    gas_k3<<<dim3(CC, DD / 256), 128>>>(x, out);
}

// round 7
// speedup vs baseline: 1.4080x; 1.4080x over previous
#include <cuda_runtime.h>

// GASLayer: per-column EMA normalization scan over T timesteps.
// Exact chunked linear-recurrence scan (3 kernels), no approximation.
// R4: K2 rewritten with double-buffered group prefetch (loads carry no chain
//     dependence -> hide all L2 latency). K1/K3 unchanged from R3.

#define TT 32768
#define DD 1024
#define LL 64
#define CC (TT / LL)   // 512 chunks

#define ETA_MU  0.01f
#define ETA_VAR 0.02f
#define A_MU (1.0f - ETA_MU)   // 0.99
#define C_V  (1.0f - ETA_VAR)  // 0.98

// Scratch: chunk-boundary partials (device globals, no allocation). ~14 MB total.
__device__ float g_sum[CC][DD];
__device__ float g_sq [CC][DD];
__device__ float g_b  [CC][DD];   // zero-init mu scan value at chunk end
__device__ float g_p0 [CC][DD];   // sum c^{L-1-t} * eta_v * e_t^2
__device__ float g_p1 [CC][DD];   // sum c^{L-1-t} * eta_v * a^{t+1} * e_t
__device__ float g_ms [CC][DD];   // exact mu at chunk entry
__device__ float g_vs [CC][DD];   // exact var-slot at chunk entry

// Pass 1: chunk-local partials. Each thread owns 2 adjacent columns.
// Grid: (CC, DD/256) = (512, 4) = 2048 blocks of 128 -> ~55 warps/SM.
__global__ __launch_bounds__(128) void gas_k1(const float* __restrict__ x) {
    const int p  = blockIdx.y * 128 + threadIdx.x;  // column-pair index 0..511
    const int c  = blockIdx.x;
    const int hd = DD / 2;
    const float2* xp = (const float2*)(x + (size_t)c * LL * DD) + p;

    float sx = 0.f, sy = 0.f, s2x = 0.f, s2y = 0.f;
    float bx = 0.f, by = 0.f, p0x = 0.f, p0y = 0.f, p1x = 0.f, p1y = 0.f;
    float w = 1.f;

    for (int t = 0; t < LL; t += 8) {
        float2 xb[8];
        #pragma unroll
        for (int u = 0; u < 8; u++) xb[u] = xp[(size_t)(t + u) * hd];
        #pragma unroll
        for (int u = 0; u < 8; u++) {
            float xv = xb[u].x, yv = xb[u].y;
            sx += xv;                 sy += yv;
            s2x = fmaf(xv, xv, s2x);  s2y = fmaf(yv, yv, s2y);
            bx  = fmaf(ETA_MU, xv - bx, bx);
            by  = fmaf(ETA_MU, yv - by, by);
            w  *= A_MU;               // w = a^{t+1}
            float ex = xv - bx, ey = yv - by;
            p0x = fmaf(ETA_VAR * ex, ex, C_V * p0x);
            p0y = fmaf(ETA_VAR * ey, ey, C_V * p0y);
            p1x = fmaf(ETA_VAR * w, ex, C_V * p1x);
            p1y = fmaf(ETA_VAR * w, ey, C_V * p1y);
        }
    }
    ((float2*)g_sum[c])[p] = make_float2(sx, sy);
    ((float2*)g_sq [c])[p] = make_float2(s2x, s2y);
    ((float2*)g_b  [c])[p] = make_float2(bx, by);
    ((float2*)g_p0 [c])[p] = make_float2(p0x, p0y);
    ((float2*)g_p1 [c])[p] = make_float2(p1x, p1y);
}

// Pass 2: mu0/std0 + exact chunk-entry state chain (CC steps per column).
// Double-buffered group prefetch: the chain deps are 1 FMA/hop; loads are
// independent of the chain and are issued a full group (16 chunks) ahead.
#define G2 16
__global__ __launch_bounds__(128) void gas_k2() {
    const int d = blockIdx.x * 128 + threadIdx.x;

    float s = 0.f, s2 = 0.f;
    #pragma unroll 16
    for (int c = 0; c < CC; c++) { s += g_sum[c][d]; s2 += g_sq[c][d]; }
    float mu0  = s * (1.0f / TT);
    float varu = (s2 - (float)TT * mu0 * mu0) * (1.0f / (TT - 1));
    float std0 = sqrtf(fmaxf(varu, 0.f));   // torch.std (unbiased), stored in var slot

    // P2 = sum_t c^{L-1-t} * eta_v * a^{2(t+1)}  (universal constant), plus a^L, c^L.
    float p2 = 0.f, w = 1.f, cLp = 1.f;
    for (int t = 0; t < LL; t++) {
        w   *= A_MU;
        p2   = fmaf(ETA_VAR * w, w, C_V * p2);
        cLp *= C_V;
    }
    const float aL = w;
    const float cL = cLp;

    float ms = mu0, vs = std0;

    float np0[G2], np1[G2], nb[G2];
    #pragma unroll
    for (int g = 0; g < G2; g++) {
        np0[g] = g_p0[g][d]; np1[g] = g_p1[g][d]; nb[g] = g_b[g][d];
    }

    for (int base = 0; base < CC; base += G2) {
        float cp0[G2], cp1[G2], cb[G2];
        #pragma unroll
        for (int g = 0; g < G2; g++) { cp0[g] = np0[g]; cp1[g] = np1[g]; cb[g] = nb[g]; }

        if (base + G2 < CC) {
            #pragma unroll
            for (int g = 0; g < G2; g++) {
                np0[g] = g_p0[base + G2 + g][d];
                np1[g] = g_p1[base + G2 + g][d];
                nb[g]  = g_b [base + G2 + g][d];
            }
        }

        #pragma unroll
        for (int g = 0; g < G2; g++) {
            const int c = base + g;
            g_ms[c][d] = ms;
            g_vs[c][d] = vs;
            float bv = fmaf(ms, fmaf(ms, p2, -2.f * cp1[g]), cp0[g]);
            vs = fmaf(cL, vs, bv);
            ms = fmaf(aL, ms, cb[g]);
        }
    }
}

// Pass 3: true recurrence from exact entry state; emit all outputs.
// float2-vectorized, 8-row prefetch (MLP=8).
// Grid: (CC, DD/256) = (512, 4) = 2048 blocks of 128 -> ~55 warps/SM.
__global__ __launch_bounds__(128) void gas_k3(const float* __restrict__ x,
                                              float* __restrict__ out) {
    const int p  = blockIdx.y * 128 + threadIdx.x;  // column-pair index 0..511
    const int c  = blockIdx.x;
    const int hd = DD / 2;

    float2 m = ((const float2*)g_ms[c])[p];
    float2 v = ((const float2*)g_vs[c])[p];

    const float2* xp    = (const float2*)(x + (size_t)c * LL * DD) + p;
    float2*       norm2 = (float2*)(out + (size_t)c * LL * DD) + p;
    // info base for this chunk: rows of [mu(D), var(D)] -> DD float2s per row
    float2*       info2 = (float2*)(out + (size_t)TT * DD + (size_t)c * LL * 2 * DD) + p;

    for (int t = 0; t < LL; t += 8) {
        float2 xb[8];
        #pragma unroll
        for (int u = 0; u < 8; u++) xb[u] = xp[(size_t)(t + u) * hd];
        #pragma unroll
        for (int u = 0; u < 8; u++) {
            float2 xv = xb[u];
            m.x = fmaf(ETA_MU, xv.x - m.x, m.x);
            m.y = fmaf(ETA_MU, xv.y - m.y, m.y);
            float rx = xv.x - m.x;
            float ry = xv.y - m.y;
            v.x = fmaf(ETA_VAR * rx, rx, C_V * v.x);
            v.y = fmaf(ETA_VAR * ry, ry, C_V * v.y);
            float2 n;
            n.x = rx * rsqrtf(v.x);
            n.y = ry * rsqrtf(v.y);
            norm2[(size_t)(t + u) * hd]      = n;
            info2[(size_t)(t + u) * DD]      = m;   // mu half of the info row
            info2[(size_t)(t + u) * DD + hd] = v;   // var half of the info row
        }
    }
}

extern "C" void kernel_launch(void* const* d_in, const int* in_sizes, int n_in,
                              void* d_out, int out_size) {
    const float* x = (const float*)d_in[0];
    float* out = (float*)d_out;

    gas_k1<<<dim3(CC, DD / 256), 128>>>(x);
    gas_k2<<<DD / 128, 128>>>();
    gas_k3<<<dim3(CC, DD / 256), 128>>>(x, out);
}